// round 16
// baseline (speedup 1.0000x reference)
#include <cuda_runtime.h>
#include <cuda_fp16.h>
#include <math.h>

// Problem constants (fixed by the dataset)
#define N_NODES 50000
#define N_EDGES 800000
#define N_TOT   (N_NODES + N_EDGES)   // edges + self loops = 850000
#define DIN  128
#define DH1  128                       // H*DH
#define DOUT 32
#define NEG_SLOPE 0.2f

#define SCAN_CHUNK 1024
#define N_CHUNKS ((N_NODES + SCAN_CHUNK - 1) / SCAN_CHUNK)   // 49

// ---------------------------------------------------------------------------
// Scratch (device globals; no runtime allocation allowed)
// ---------------------------------------------------------------------------
__device__ int   g_is64;               // 1 if edge_index buffer is int64
__device__ int   g_deg[N_NODES];
__device__ int   g_rowptr[N_NODES + 1];
__device__ int   g_cursor[N_NODES];
__device__ int   g_col[N_TOT];
__device__ int   g_blksum[N_CHUNKS];

__device__ __align__(16) float g_xs1[N_NODES * DH1];   // x @ W1_src + b1_src
__device__ __align__(16) float g_xd1[N_NODES * DH1];   // x @ W1_dst + b1_dst
__device__ __align__(16) float g_h1 [N_NODES * DH1];   // elu(gat1 out + bias1)
__device__ __align__(16) float g_xs2[N_NODES * DOUT];
__device__ __align__(16) float g_xd2[N_NODES * DOUT];

// Pre-transposed fp16 weights, column-major: Wt[c][k]
__device__ __align__(16) __half g_W1t[256 * 128];
__device__ __align__(16) __half g_W2t[64 * 128];

__device__ __forceinline__ float lrelu(float v) {
    return v > 0.f ? v : NEG_SLOPE * v;
}
__device__ __forceinline__ float eluf(float v) {
    return v > 0.f ? v : expm1f(v);
}
// m16n8k16 fp16 HMMA, fp32 accumulate.
__device__ __forceinline__ void mma_f16(float* c, const unsigned* a, const unsigned* b) {
    asm volatile(
        "mma.sync.aligned.m16n8k16.row.col.f32.f16.f16.f32 "
        "{%0,%1,%2,%3}, {%4,%5,%6,%7}, {%8,%9}, {%0,%1,%2,%3};\n"
        : "+f"(c[0]), "+f"(c[1]), "+f"(c[2]), "+f"(c[3])
        : "r"(a[0]), "r"(a[1]), "r"(a[2]), "r"(a[3]), "r"(b[0]), "r"(b[1]));
}
// ldmatrix x4: one 16x16 fp16 A-tile -> m16n8k16 A fragment (a0..a3).
__device__ __forceinline__ void ldsm_x4(unsigned* a, unsigned addr) {
    asm volatile(
        "ldmatrix.sync.aligned.m8n8.x4.shared.b16 {%0,%1,%2,%3}, [%4];"
        : "=r"(a[0]), "=r"(a[1]), "=r"(a[2]), "=r"(a[3]) : "r"(addr));
}
// cp.async 16B global->shared (LDGSTS), no in-flight register cost.
__device__ __forceinline__ void cp_async16(unsigned saddr, const void* gptr) {
    asm volatile("cp.async.cg.shared.global [%0], [%1], 16;"
                 :: "r"(saddr), "l"(gptr));
}
__device__ __forceinline__ void cp_commit() {
    asm volatile("cp.async.commit_group;");
}
__device__ __forceinline__ void cp_wait1() {
    asm volatile("cp.async.wait_group 1;");
}

__device__ __forceinline__ int edge_at(const int* __restrict__ ei32,
                                       int row, int e, int is64) {
    if (is64) {
        return ((const int2*)ei32)[row * (long long)N_EDGES + e].x;
    } else {
        return ei32[row * N_EDGES + e];
    }
}

// ---------------------------------------------------------------------------
// Init: degree = 1 (self-loop pre-counted) + dtype detection (block 0).
// ---------------------------------------------------------------------------
__global__ void k_init(const int* __restrict__ ei32) {
    int i = blockIdx.x * blockDim.x + threadIdx.x;
    if (i < N_NODES) g_deg[i] = 1;
    if (blockIdx.x == 0) {
        __shared__ int nz;
        if (threadIdx.x == 0) nz = 0;
        __syncthreads();
        const int SAMPLES = 4096;
        const int stride = N_EDGES / SAMPLES;   // 195
        for (int k = threadIdx.x; k < SAMPLES; k += blockDim.x) {
            if (ei32[2 * (k * stride) + 1] != 0) nz = 1;
        }
        __syncthreads();
        if (threadIdx.x == 0) g_is64 = (nz == 0) ? 1 : 0;
    }
}

// ---------------------------------------------------------------------------
// Weight prep: transpose + convert all W to fp16 column-major.
// ---------------------------------------------------------------------------
__global__ void k_prep(const float* __restrict__ W1s, const float* __restrict__ W1d,
                       const float* __restrict__ W2s, const float* __restrict__ W2d)
{
    int idx = blockIdx.x * blockDim.x + threadIdx.x;
    if (idx < 256 * 128) {
        int c = idx >> 7, k = idx & 127;
        float v = (c < 128) ? W1s[k * 128 + c] : W1d[k * 128 + (c - 128)];
        g_W1t[idx] = __float2half_rn(v);
    }
    if (idx < 64 * 128) {
        int c = idx >> 7, k = idx & 127;
        float v = (c < 32) ? W2s[k * 32 + c] : W2d[k * 32 + (c - 32)];
        g_W2t[idx] = __float2half_rn(v);
    }
}

// ---------------------------------------------------------------------------
// CSR construction (real edges only; self-loops placed in k_scan3).
// ---------------------------------------------------------------------------
__global__ void k_hist(const int* __restrict__ ei32) {
    int e = blockIdx.x * blockDim.x + threadIdx.x;
    if (e >= N_EDGES) return;
    int is64 = g_is64;
    int dst = edge_at(ei32, 1, e, is64);
    if ((unsigned)dst < (unsigned)N_NODES)
        atomicAdd(&g_deg[dst], 1);
}

__global__ __launch_bounds__(SCAN_CHUNK) void k_scan1() {
    __shared__ int ws[32];
    int b = blockIdx.x, t = threadIdx.x;
    int i = b * SCAN_CHUNK + t;
    int v = (i < N_NODES) ? g_deg[i] : 0;
    int x = v;
    #pragma unroll
    for (int d = 1; d < 32; d <<= 1) {
        int y = __shfl_up_sync(0xffffffffu, x, d);
        if ((t & 31) >= d) x += y;
    }
    if ((t & 31) == 31) ws[t >> 5] = x;
    __syncthreads();
    if (t < 32) {
        int y = ws[t];
        #pragma unroll
        for (int d = 1; d < 32; d <<= 1) {
            int z = __shfl_up_sync(0xffffffffu, y, d);
            if (t >= d) y += z;
        }
        ws[t] = y;
    }
    __syncthreads();
    int off = (t >= 32) ? ws[(t >> 5) - 1] : 0;
    int incl = off + x;
    if (i < N_NODES) g_rowptr[i] = incl - v;
    if (t == SCAN_CHUNK - 1) g_blksum[b] = incl;
}

__global__ __launch_bounds__(SCAN_CHUNK) void k_scan3() {
    __shared__ int s[N_CHUNKS + 1];
    int b = blockIdx.x, t = threadIdx.x;
    if (t < N_CHUNKS) s[t] = g_blksum[t];
    __syncthreads();
    if (t == 0) {
        int run = 0;
        #pragma unroll 7
        for (int i = 0; i < N_CHUNKS; i++) { int v = s[i]; s[i] = run; run += v; }
        s[N_CHUNKS] = run;
    }
    __syncthreads();
    int i = b * SCAN_CHUNK + t;
    if (i < N_NODES) {
        int r = g_rowptr[i] + s[b];
        g_rowptr[i] = r;
        g_col[r] = i;
        g_cursor[i] = r + 1;
    }
    if (b == N_CHUNKS - 1 && t == 0) g_rowptr[N_NODES] = s[N_CHUNKS];
}

__global__ void k_scatter(const int* __restrict__ ei32) {
    int e = blockIdx.x * blockDim.x + threadIdx.x;
    if (e >= N_EDGES) return;
    int is64 = g_is64;
    int src = edge_at(ei32, 0, e, is64);
    int dst = edge_at(ei32, 1, e, is64);
    if ((unsigned)dst >= (unsigned)N_NODES) return;
    if ((unsigned)src >= (unsigned)N_NODES) src = 0;
    int pos = atomicAdd(&g_cursor[dst], 1);
    g_col[pos] = src;
}

// ---------------------------------------------------------------------------
// GEMM 1 (fp16 HMMA m16n8k16, ldmatrix A): [xs1|xd1] = x @ [W1_src|W1_dst]
// ---------------------------------------------------------------------------
__global__ __launch_bounds__(256, 2) void k_gemm1(
    const float* __restrict__ x,
    const float* __restrict__ bsrc, const float* __restrict__ bdst)
{
    __shared__ __half sAh[64][136];
    int r0 = blockIdx.x * 64;
    int t = threadIdx.x;

    #pragma unroll
    for (int i = 0; i < 8; i++) {
        int idx = t + i * 256;
        int row = idx >> 5;
        int c4  = idx & 31;
        float4 v = make_float4(0.f, 0.f, 0.f, 0.f);
        if (r0 + row < N_NODES) v = ((const float4*)x)[(r0 + row) * 32 + c4];
        *(__half2*)&sAh[row][c4 * 4]     = __floats2half2_rn(v.x, v.y);
        *(__half2*)&sAh[row][c4 * 4 + 2] = __floats2half2_rn(v.z, v.w);
    }
    __syncthreads();

    int lane   = t & 31;
    int wid    = t >> 5;
    int warp_m = wid & 1;
    int warp_n = wid >> 1;
    int qid    = lane >> 2;
    int tid4   = lane & 3;

    int cbase = warp_n * 64;

    int lrow = (lane & 7) + ((lane >> 3) & 1) * 8;
    int lcol = ((lane >> 4) & 1) * 8;
    unsigned sbase = (unsigned)__cvta_generic_to_shared(&sAh[0][0]);
    unsigned aaddr0 = sbase + (unsigned)(((warp_m * 32 + lrow) * 136 + lcol) * 2);

    float acc[2][8][4];
    #pragma unroll
    for (int mt = 0; mt < 2; mt++)
        #pragma unroll
        for (int nt = 0; nt < 8; nt++)
            #pragma unroll
            for (int i = 0; i < 4; i++) acc[mt][nt][i] = 0.f;

    #pragma unroll 4
    for (int ks = 0; ks < 8; ks++) {
        int k0 = ks * 16;
        unsigned a[2][4];
        ldsm_x4(a[0], aaddr0 + (unsigned)(k0 * 2));
        ldsm_x4(a[1], aaddr0 + (unsigned)((16 * 136 + k0) * 2));

        unsigned b[8][2];
        #pragma unroll
        for (int nt = 0; nt < 8; nt++) {
            int cc = cbase + nt * 8 + qid;
            b[nt][0] = *(const unsigned*)&g_W1t[cc * 128 + k0 + 2 * tid4    ];
            b[nt][1] = *(const unsigned*)&g_W1t[cc * 128 + k0 + 2 * tid4 + 8];
        }
        #pragma unroll
        for (int mt = 0; mt < 2; mt++)
            #pragma unroll
            for (int nt = 0; nt < 8; nt++)
                mma_f16(acc[mt][nt], a[mt], b[nt]);
    }

    float* outp = (warp_n < 2) ? g_xs1 : g_xd1;
    const float* bp = (warp_n < 2) ? bsrc : bdst;
    int cloc = (warp_n & 1) * 64;
    #pragma unroll
    for (int mt = 0; mt < 2; mt++) {
        int row = r0 + warp_m * 32 + mt * 16 + qid;
        #pragma unroll
        for (int nt = 0; nt < 8; nt++) {
            int cc = cloc + nt * 8 + 2 * tid4;
            float b0v = bp[cc], b1v = bp[cc + 1];
            if (row < N_NODES) {
                float2 v = make_float2(acc[mt][nt][0] + b0v, acc[mt][nt][1] + b1v);
                *(float2*)&outp[row * 128 + cc] = v;
            }
            if (row + 8 < N_NODES) {
                float2 v = make_float2(acc[mt][nt][2] + b0v, acc[mt][nt][3] + b1v);
                *(float2*)&outp[(row + 8) * 128 + cc] = v;
            }
        }
    }
}

// ---------------------------------------------------------------------------
// Edge phase, layer 1: one warp per node, cp.async DOUBLE-BUFFERED gathers.
// Per chunk (8 edges): each lane issues 8x cp.async (16B) into its own smem
// slice for chunk i+1 while chunk i is computed from smem. No msg[] register
// pressure in flight; per-thread wait_group; no cross-lane smem sharing.
// Block = 128 thr = 4 warps = 4 nodes. smem: 4*2*8*32*16B + col window = 33KB.
// ---------------------------------------------------------------------------
#define EC1 8
__global__ __launch_bounds__(128) void k_edge1(
    const float* __restrict__ att, const float* __restrict__ bias)
{
    __shared__ float4 sbuf[4][2][EC1][32];
    __shared__ int s_col[4][32];

    int t = threadIdx.x;
    int wid  = t >> 5;
    int lane = t & 31;
    int node = blockIdx.x * 4 + wid;
    if (node >= N_NODES) return;   // warp-uniform

    float4 xd = ((const float4*)g_xd1)[node * 32 + lane];
    float4 av = ((const float4*)att)[lane];

    float den = 0.f;
    float4 acc = make_float4(0.f, 0.f, 0.f, 0.f);

    int j    = g_rowptr[node];
    int jend = g_rowptr[node + 1];   // deg >= 1

    unsigned bufaddr =
        (unsigned)__cvta_generic_to_shared(&sbuf[wid][0][0][lane]);
    const unsigned BUF_STRIDE  = EC1 * 32 * 16;   // bytes between buffers
    const unsigned EDGE_STRIDE = 32 * 16;         // bytes between edges

    // Stage column window [win, win+32)
    int win = j;
    int wm = min(32, jend - win);
    if (lane < wm) s_col[wid][lane] = g_col[win + lane];
    __syncwarp();

    // Prologue: issue chunk 0 into buffer 0
    {
        int m = min(EC1, jend - j);
        for (int k = 0; k < m; k++) {
            int s = s_col[wid][(j - win) + k];
            cp_async16(bufaddr + (unsigned)k * EDGE_STRIDE,
                       ((const float4*)g_xs1) + s * 32 + lane);
        }
        cp_commit();
    }

    int cur = 0;
    while (j < jend) {
        int m  = min(EC1, jend - j);
        int jn = j + m;
        int mn = (jn < jend) ? min(EC1, jend - jn) : 0;

        // Issue next chunk into the other buffer (restage col window if needed)
        if (mn > 0) {
            if (jn - win >= 32) {
                win += 32;
                int wm2 = min(32, jend - win);
                __syncwarp();
                if (lane < wm2) s_col[wid][lane] = g_col[win + lane];
                __syncwarp();
            }
            unsigned dst = bufaddr + (unsigned)(cur ^ 1) * BUF_STRIDE;
            for (int k = 0; k < mn; k++) {
                int s = s_col[wid][(jn - win) + k];
                cp_async16(dst + (unsigned)k * EDGE_STRIDE,
                           ((const float4*)g_xs1) + s * 32 + lane);
            }
        }
        cp_commit();
        cp_wait1();   // current chunk's group complete (per-thread)

        const float4* mb = &sbuf[wid][cur][0][lane];   // stride 32 float4 per k

        if (m == EC1) {
            float p[EC1];
            #pragma unroll
            for (int k = 0; k < EC1; k++) {
                float4 mg = mb[k * 32];
                float e0 = lrelu(mg.x + xd.x);
                float e1 = lrelu(mg.y + xd.y);
                float e2 = lrelu(mg.z + xd.z);
                float e3 = lrelu(mg.w + xd.w);
                p[k] = fmaf(av.x, e0, fmaf(av.y, e1, fmaf(av.z, e2, av.w * e3)));
            }
            #pragma unroll
            for (int k = 0; k < EC1; k++)
                p[k] += __shfl_xor_sync(0xffffffffu, p[k], 1);
            #pragma unroll
            for (int k = 0; k < EC1; k++)
                p[k] += __shfl_xor_sync(0xffffffffu, p[k], 2);
            #pragma unroll
            for (int k = 0; k < EC1; k++) {
                float4 mg = mb[k * 32];
                float w = __expf(p[k]);
                den += w;
                acc.x = fmaf(w, mg.x, acc.x);
                acc.y = fmaf(w, mg.y, acc.y);
                acc.z = fmaf(w, mg.z, acc.z);
                acc.w = fmaf(w, mg.w, acc.w);
            }
        } else {
            for (int k = 0; k < m; k++) {
                float4 mg = mb[k * 32];
                float e0 = lrelu(mg.x + xd.x);
                float e1 = lrelu(mg.y + xd.y);
                float e2 = lrelu(mg.z + xd.z);
                float e3 = lrelu(mg.w + xd.w);
                float p = fmaf(av.x, e0, fmaf(av.y, e1, fmaf(av.z, e2, av.w * e3)));
                p += __shfl_xor_sync(0xffffffffu, p, 1);
                p += __shfl_xor_sync(0xffffffffu, p, 2);
                float w = __expf(p);
                den += w;
                acc.x = fmaf(w, mg.x, acc.x);
                acc.y = fmaf(w, mg.y, acc.y);
                acc.z = fmaf(w, mg.z, acc.z);
                acc.w = fmaf(w, mg.w, acc.w);
            }
        }

        j = jn;
        cur ^= 1;
    }

    float inv = 1.0f / den;
    float4 b = ((const float4*)bias)[lane];
    float4 o;
    o.x = eluf(fmaf(acc.x, inv, b.x));
    o.y = eluf(fmaf(acc.y, inv, b.y));
    o.z = eluf(fmaf(acc.z, inv, b.z));
    o.w = eluf(fmaf(acc.w, inv, b.w));
    ((float4*)g_h1)[node * 32 + lane] = o;
}

// ---------------------------------------------------------------------------
// GEMM 2 (fp16 HMMA m16n8k16, ldmatrix A): [xs2|xd2] = h1 @ [W2_src|W2_dst]
// ---------------------------------------------------------------------------
__global__ __launch_bounds__(256, 2) void k_gemm2(
    const float* __restrict__ bsrc, const float* __restrict__ bdst)
{
    __shared__ __half sAh[64][136];
    int r0 = blockIdx.x * 64;
    int t = threadIdx.x;

    #pragma unroll
    for (int i = 0; i < 8; i++) {
        int idx = t + i * 256;
        int row = idx >> 5;
        int c4  = idx & 31;
        float4 v = make_float4(0.f, 0.f, 0.f, 0.f);
        if (r0 + row < N_NODES) v = ((const float4*)g_h1)[(r0 + row) * 32 + c4];
        *(__half2*)&sAh[row][c4 * 4]     = __floats2half2_rn(v.x, v.y);
        *(__half2*)&sAh[row][c4 * 4 + 2] = __floats2half2_rn(v.z, v.w);
    }
    __syncthreads();

    int lane   = t & 31;
    int wid    = t >> 5;
    int warp_m = wid & 3;
    int warp_n = wid >> 2;
    int qid    = lane >> 2;
    int tid4   = lane & 3;

    int cbase = warp_n * 32;

    int lrow = (lane & 7) + ((lane >> 3) & 1) * 8;
    int lcol = ((lane >> 4) & 1) * 8;
    unsigned sbase = (unsigned)__cvta_generic_to_shared(&sAh[0][0]);
    unsigned aaddr0 = sbase + (unsigned)(((warp_m * 16 + lrow) * 136 + lcol) * 2);

    float acc[4][4];
    #pragma unroll
    for (int nt = 0; nt < 4; nt++)
        #pragma unroll
        for (int i = 0; i < 4; i++) acc[nt][i] = 0.f;

    #pragma unroll 4
    for (int ks = 0; ks < 8; ks++) {
        int k0 = ks * 16;
        unsigned a[4];
        ldsm_x4(a, aaddr0 + (unsigned)(k0 * 2));

        unsigned b[4][2];
        #pragma unroll
        for (int nt = 0; nt < 4; nt++) {
            int cc = cbase + nt * 8 + qid;
            b[nt][0] = *(const unsigned*)&g_W2t[cc * 128 + k0 + 2 * tid4    ];
            b[nt][1] = *(const unsigned*)&g_W2t[cc * 128 + k0 + 2 * tid4 + 8];
        }
        #pragma unroll
        for (int nt = 0; nt < 4; nt++)
            mma_f16(acc[nt], a, b[nt]);
    }

    float* outp = warp_n ? g_xd2 : g_xs2;
    const float* bp = warp_n ? bdst : bsrc;
    int row = r0 + warp_m * 16 + qid;
    #pragma unroll
    for (int nt = 0; nt < 4; nt++) {
        int cc = nt * 8 + 2 * tid4;
        float b0v = bp[cc], b1v = bp[cc + 1];
        if (row < N_NODES) {
            float2 v = make_float2(acc[nt][0] + b0v, acc[nt][1] + b1v);
            *(float2*)&outp[row * 32 + cc] = v;
        }
        if (row + 8 < N_NODES) {
            float2 v = make_float2(acc[nt][2] + b0v, acc[nt][3] + b1v);
            *(float2*)&outp[(row + 8) * 32 + cc] = v;
        }
    }
}

// ---------------------------------------------------------------------------
// Edge phase, layer 2 (round-8 body, frozen). Fused bias2 + log_softmax.
// ---------------------------------------------------------------------------
#define EC2 8
__global__ __launch_bounds__(256) void k_edge2(
    const float* __restrict__ att, const float* __restrict__ bias,
    float* __restrict__ out)
{
    int g = blockIdx.x * blockDim.x + threadIdx.x;
    int node = g >> 5;
    if (node >= N_NODES) return;
    int lane = g & 31;

    float xd = g_xd2[node * 32 + lane];
    float av = att[lane];

    float den = 0.f, acc = 0.f;

    int j    = g_rowptr[node];
    int jend = g_rowptr[node + 1];

    for (; j + EC2 <= jend; j += EC2) {
        float msg[EC2], p[EC2];
        #pragma unroll
        for (int k = 0; k < EC2; k++) {
            int s = g_col[j + k];
            msg[k] = g_xs2[s * 32 + lane];
        }
        #pragma unroll
        for (int k = 0; k < EC2; k++)
            p[k] = av * lrelu(msg[k] + xd);
        #pragma unroll
        for (int d = 1; d < 32; d <<= 1) {
            #pragma unroll
            for (int k = 0; k < EC2; k++)
                p[k] += __shfl_xor_sync(0xffffffffu, p[k], d);
        }
        #pragma unroll
        for (int k = 0; k < EC2; k++) {
            float w = __expf(p[k]);
            den += w;
            acc = fmaf(w, msg[k], acc);
        }
    }

    for (; j < jend; ++j) {
        int s = g_col[j];
        float msg = g_xs2[s * 32 + lane];
        float p = av * lrelu(msg + xd);
        #pragma unroll
        for (int d = 1; d < 32; d <<= 1)
            p += __shfl_xor_sync(0xffffffffu, p, d);
        float w = __expf(p);
        den += w;
        acc = fmaf(w, msg, acc);
    }

    float v = acc / den + bias[lane];

    float mx = v;
    #pragma unroll
    for (int d = 1; d < 32; d <<= 1)
        mx = fmaxf(mx, __shfl_xor_sync(0xffffffffu, mx, d));
    float ex = expf(v - mx);
    float ssum = ex;
    #pragma unroll
    for (int d = 1; d < 32; d <<= 1)
        ssum += __shfl_xor_sync(0xffffffffu, ssum, d);

    out[node * 32 + lane] = v - mx - logf(ssum);
}

// ---------------------------------------------------------------------------
// Launch: fork CSR || prep+gemm1; then edge1 -> gemm2 -> edge2.
// ---------------------------------------------------------------------------
extern "C" void kernel_launch(void* const* d_in, const int* in_sizes, int n_in,
                              void* d_out, int out_size)
{
    const float* x     = (const float*)d_in[0];
    const int*   ei32  = (const int*)d_in[1];   // int32 OR int64 (detected)
    const float* W1s   = (const float*)d_in[2];
    const float* W1d   = (const float*)d_in[3];
    const float* b1s   = (const float*)d_in[4];
    const float* b1d   = (const float*)d_in[5];
    const float* att1  = (const float*)d_in[6];
    const float* bias1 = (const float*)d_in[7];
    const float* W2s   = (const float*)d_in[8];
    const float* W2d   = (const float*)d_in[9];
    const float* b2s   = (const float*)d_in[10];
    const float* b2d   = (const float*)d_in[11];
    const float* att2  = (const float*)d_in[12];
    const float* bias2 = (const float*)d_in[13];
    float* out = (float*)d_out;

    static cudaStream_t s2 = nullptr;
    static cudaEvent_t evFork = nullptr, evJoin = nullptr;
    if (s2 == nullptr) {
        cudaStreamCreateWithFlags(&s2, cudaStreamNonBlocking);
        cudaEventCreateWithFlags(&evFork, cudaEventDisableTiming);
        cudaEventCreateWithFlags(&evJoin, cudaEventDisableTiming);
    }

    // Fork: side stream runs weight prep + gemm1 (independent of CSR).
    cudaEventRecord(evFork, 0);
    cudaStreamWaitEvent(s2, evFork, 0);
    k_prep<<<(256 * 128 + 255) / 256, 256, 0, s2>>>(W1s, W1d, W2s, W2d);
    k_gemm1<<<(N_NODES + 63) / 64, 256, 0, s2>>>(x, b1s, b1d);
    cudaEventRecord(evJoin, s2);

    // Main stream: CSR build chain.
    k_init<<<(N_NODES + 255) / 256, 256>>>(ei32);
    k_hist<<<(N_EDGES + 255) / 256, 256>>>(ei32);
    k_scan1<<<N_CHUNKS, SCAN_CHUNK>>>();
    k_scan3<<<N_CHUNKS, SCAN_CHUNK>>>();
    k_scatter<<<(N_EDGES + 255) / 256, 256>>>(ei32);

    // Join: edge1 needs both CSR and gemm1 outputs.
    cudaStreamWaitEvent(0, evJoin, 0);
    k_edge1<<<(N_NODES + 3) / 4, 128>>>(att1, bias1);

    // Layer 2
    k_gemm2<<<(N_NODES + 63) / 64, 256>>>(b2s, b2d);
    k_edge2<<<(N_NODES * 32 + 255) / 256, 256>>>(att2, bias2, out);
}

// round 17
// speedup vs baseline: 1.0494x; 1.0494x over previous
#include <cuda_runtime.h>
#include <cuda_fp16.h>
#include <math.h>

// Problem constants (fixed by the dataset)
#define N_NODES 50000
#define N_EDGES 800000
#define N_TOT   (N_NODES + N_EDGES)   // edges + self loops = 850000
#define DIN  128
#define DH1  128                       // H*DH
#define DOUT 32
#define NEG_SLOPE 0.2f

#define SCAN_CHUNK 1024
#define N_CHUNKS ((N_NODES + SCAN_CHUNK - 1) / SCAN_CHUNK)   // 49

// ---------------------------------------------------------------------------
// Scratch (device globals; no runtime allocation allowed)
// ---------------------------------------------------------------------------
__device__ int   g_is64;               // 1 if edge_index buffer is int64
__device__ int   g_deg[N_NODES];
__device__ int   g_rowptr[N_NODES + 1];
__device__ int   g_cursor[N_NODES];
__device__ int   g_col[N_TOT];
__device__ int   g_blksum[N_CHUNKS];

__device__ __align__(16) float g_xs1[N_NODES * DH1];   // x @ W1_src + b1_src
__device__ __align__(16) float g_xd1[N_NODES * DH1];   // x @ W1_dst + b1_dst
__device__ __align__(16) float g_h1 [N_NODES * DH1];   // elu(gat1 out + bias1)
__device__ __align__(16) float g_xs2[N_NODES * DOUT];
__device__ __align__(16) float g_xd2[N_NODES * DOUT];

// Pre-transposed fp16 weights, column-major: Wt[c][k]
__device__ __align__(16) __half g_W1t[256 * 128];   // cols 0-127: W1_src, 128-255: W1_dst
__device__ __align__(16) __half g_W2t[64 * 128];    // cols 0-31:  W2_src, 32-63:   W2_dst

__device__ __forceinline__ float lrelu(float v) {
    return v > 0.f ? v : NEG_SLOPE * v;
}
__device__ __forceinline__ float eluf(float v) {
    return v > 0.f ? v : expm1f(v);
}
// m16n8k16 fp16 HMMA, fp32 accumulate.
__device__ __forceinline__ void mma_f16(float* c, const unsigned* a, const unsigned* b) {
    asm volatile(
        "mma.sync.aligned.m16n8k16.row.col.f32.f16.f16.f32 "
        "{%0,%1,%2,%3}, {%4,%5,%6,%7}, {%8,%9}, {%0,%1,%2,%3};\n"
        : "+f"(c[0]), "+f"(c[1]), "+f"(c[2]), "+f"(c[3])
        : "r"(a[0]), "r"(a[1]), "r"(a[2]), "r"(a[3]), "r"(b[0]), "r"(b[1]));
}

__device__ __forceinline__ int edge_at(const int* __restrict__ ei32,
                                       int row, int e, int is64) {
    if (is64) {
        return ((const int2*)ei32)[row * (long long)N_EDGES + e].x;
    } else {
        return ei32[row * N_EDGES + e];
    }
}

// ---------------------------------------------------------------------------
// Init: zero degree counters + dtype detection (block 0).
// ---------------------------------------------------------------------------
__global__ void k_init(const int* __restrict__ ei32) {
    int i = blockIdx.x * blockDim.x + threadIdx.x;
    if (i < N_NODES) g_deg[i] = 0;
    if (blockIdx.x == 0) {
        __shared__ int nz;
        if (threadIdx.x == 0) nz = 0;
        __syncthreads();
        const int SAMPLES = 4096;
        const int stride = N_EDGES / SAMPLES;   // 195
        for (int k = threadIdx.x; k < SAMPLES; k += blockDim.x) {
            if (ei32[2 * (k * stride) + 1] != 0) nz = 1;
        }
        __syncthreads();
        if (threadIdx.x == 0) g_is64 = (nz == 0) ? 1 : 0;
    }
}

// ---------------------------------------------------------------------------
// Weight prep: transpose + convert all W to fp16 column-major.
// ---------------------------------------------------------------------------
__global__ void k_prep(const float* __restrict__ W1s, const float* __restrict__ W1d,
                       const float* __restrict__ W2s, const float* __restrict__ W2d)
{
    int idx = blockIdx.x * blockDim.x + threadIdx.x;
    if (idx < 256 * 128) {
        int c = idx >> 7, k = idx & 127;
        float v = (c < 128) ? W1s[k * 128 + c] : W1d[k * 128 + (c - 128)];
        g_W1t[idx] = __float2half_rn(v);
    }
    if (idx < 64 * 128) {
        int c = idx >> 7, k = idx & 127;
        float v = (c < 32) ? W2s[k * 32 + c] : W2d[k * 32 + (c - 32)];
        g_W2t[idx] = __float2half_rn(v);
    }
}

// ---------------------------------------------------------------------------
// CSR construction (by destination node)
// ---------------------------------------------------------------------------
__global__ void k_hist(const int* __restrict__ ei32) {
    int e = blockIdx.x * blockDim.x + threadIdx.x;
    if (e >= N_TOT) return;
    int is64 = g_is64;
    int dst = (e < N_EDGES) ? edge_at(ei32, 1, e, is64) : (e - N_EDGES);
    if ((unsigned)dst < (unsigned)N_NODES)
        atomicAdd(&g_deg[dst], 1);
}

// Pass 1: per-chunk exclusive scan (local) + chunk totals.
__global__ __launch_bounds__(SCAN_CHUNK) void k_scan1() {
    __shared__ int ws[32];
    int b = blockIdx.x, t = threadIdx.x;
    int i = b * SCAN_CHUNK + t;
    int v = (i < N_NODES) ? g_deg[i] : 0;
    int x = v;
    #pragma unroll
    for (int d = 1; d < 32; d <<= 1) {
        int y = __shfl_up_sync(0xffffffffu, x, d);
        if ((t & 31) >= d) x += y;
    }
    if ((t & 31) == 31) ws[t >> 5] = x;
    __syncthreads();
    if (t < 32) {
        int y = ws[t];
        #pragma unroll
        for (int d = 1; d < 32; d <<= 1) {
            int z = __shfl_up_sync(0xffffffffu, y, d);
            if (t >= d) y += z;
        }
        ws[t] = y;
    }
    __syncthreads();
    int off = (t >= 32) ? ws[(t >> 5) - 1] : 0;
    int incl = off + x;
    if (i < N_NODES) g_rowptr[i] = incl - v;     // chunk-local exclusive
    if (t == SCAN_CHUNK - 1) g_blksum[b] = incl; // chunk total
}

// Pass 2 (merged): every block serial-scans the 49 chunk totals in smem,
// then adds its chunk's offset.
__global__ __launch_bounds__(SCAN_CHUNK) void k_scan3() {
    __shared__ int s[N_CHUNKS + 1];
    int b = blockIdx.x, t = threadIdx.x;
    if (t < N_CHUNKS) s[t] = g_blksum[t];
    __syncthreads();
    if (t == 0) {
        int run = 0;
        #pragma unroll 7
        for (int i = 0; i < N_CHUNKS; i++) { int v = s[i]; s[i] = run; run += v; }
        s[N_CHUNKS] = run;   // grand total
    }
    __syncthreads();
    int i = b * SCAN_CHUNK + t;
    if (i < N_NODES) {
        int r = g_rowptr[i] + s[b];
        g_rowptr[i] = r;
        g_cursor[i] = r;
    }
    if (b == N_CHUNKS - 1 && t == 0) g_rowptr[N_NODES] = s[N_CHUNKS];
}

__global__ void k_scatter(const int* __restrict__ ei32) {
    int e = blockIdx.x * blockDim.x + threadIdx.x;
    if (e >= N_TOT) return;
    int is64 = g_is64;
    int src, dst;
    if (e < N_EDGES) {
        src = edge_at(ei32, 0, e, is64);
        dst = edge_at(ei32, 1, e, is64);
    } else {
        src = dst = e - N_EDGES;
    }
    if ((unsigned)dst >= (unsigned)N_NODES) return;
    if ((unsigned)src >= (unsigned)N_NODES) src = 0;
    int pos = atomicAdd(&g_cursor[dst], 1);
    g_col[pos] = src;
}

// ---------------------------------------------------------------------------
// GEMM 1 (fp16 HMMA m16n8k16): [xs1|xd1] = x[50000,128] @ [W1_src|W1_dst]
// ---------------------------------------------------------------------------
__global__ __launch_bounds__(256, 2) void k_gemm1(
    const float* __restrict__ x,
    const float* __restrict__ bsrc, const float* __restrict__ bdst)
{
    __shared__ __half sAh[64][136];
    int r0 = blockIdx.x * 64;
    int t = threadIdx.x;

    #pragma unroll
    for (int i = 0; i < 8; i++) {
        int idx = t + i * 256;
        int row = idx >> 5;
        int c4  = idx & 31;
        float4 v = make_float4(0.f, 0.f, 0.f, 0.f);
        if (r0 + row < N_NODES) v = ((const float4*)x)[(r0 + row) * 32 + c4];
        *(__half2*)&sAh[row][c4 * 4]     = __floats2half2_rn(v.x, v.y);
        *(__half2*)&sAh[row][c4 * 4 + 2] = __floats2half2_rn(v.z, v.w);
    }
    __syncthreads();

    int lane   = t & 31;
    int wid    = t >> 5;
    int warp_m = wid & 1;
    int warp_n = wid >> 1;
    int qid    = lane >> 2;
    int tid4   = lane & 3;

    int cbase = warp_n * 64;

    float acc[2][8][4];
    #pragma unroll
    for (int mt = 0; mt < 2; mt++)
        #pragma unroll
        for (int nt = 0; nt < 8; nt++)
            #pragma unroll
            for (int i = 0; i < 4; i++) acc[mt][nt][i] = 0.f;

    #pragma unroll 4
    for (int ks = 0; ks < 8; ks++) {
        int k0 = ks * 16;
        unsigned a[2][4];
        #pragma unroll
        for (int mt = 0; mt < 2; mt++) {
            int rb = warp_m * 32 + mt * 16;
            a[mt][0] = *(const unsigned*)&sAh[rb + qid    ][k0 + 2 * tid4    ];
            a[mt][1] = *(const unsigned*)&sAh[rb + qid + 8][k0 + 2 * tid4    ];
            a[mt][2] = *(const unsigned*)&sAh[rb + qid    ][k0 + 2 * tid4 + 8];
            a[mt][3] = *(const unsigned*)&sAh[rb + qid + 8][k0 + 2 * tid4 + 8];
        }
        unsigned b[8][2];
        #pragma unroll
        for (int nt = 0; nt < 8; nt++) {
            int cc = cbase + nt * 8 + qid;
            b[nt][0] = *(const unsigned*)&g_W1t[cc * 128 + k0 + 2 * tid4    ];
            b[nt][1] = *(const unsigned*)&g_W1t[cc * 128 + k0 + 2 * tid4 + 8];
        }
        #pragma unroll
        for (int mt = 0; mt < 2; mt++)
            #pragma unroll
            for (int nt = 0; nt < 8; nt++)
                mma_f16(acc[mt][nt], a[mt], b[nt]);
    }

    float* outp = (warp_n < 2) ? g_xs1 : g_xd1;
    const float* bp = (warp_n < 2) ? bsrc : bdst;
    int cloc = (warp_n & 1) * 64;
    #pragma unroll
    for (int mt = 0; mt < 2; mt++) {
        int row = r0 + warp_m * 32 + mt * 16 + qid;
        #pragma unroll
        for (int nt = 0; nt < 8; nt++) {
            int cc = cloc + nt * 8 + 2 * tid4;
            float b0v = bp[cc], b1v = bp[cc + 1];
            if (row < N_NODES) {
                float2 v = make_float2(acc[mt][nt][0] + b0v, acc[mt][nt][1] + b1v);
                *(float2*)&outp[row * 128 + cc] = v;
            }
            if (row + 8 < N_NODES) {
                float2 v = make_float2(acc[mt][nt][2] + b0v, acc[mt][nt][3] + b1v);
                *(float2*)&outp[(row + 8) * 128 + cc] = v;
            }
        }
    }
}

// ---------------------------------------------------------------------------
// Edge phase, layer 1: one warp per destination node, NO-shift softmax
// (shift-invariance: logits bounded ~|10| here, exp is safe in fp32).
// lane l owns elements [4l, 4l+4) -> head l/4. Fused bias1 + ELU.
// ---------------------------------------------------------------------------
#define EC1 8
__global__ __launch_bounds__(256) void k_edge1(
    const float* __restrict__ att, const float* __restrict__ bias)
{
    int g = blockIdx.x * blockDim.x + threadIdx.x;
    int node = g >> 5;
    if (node >= N_NODES) return;
    int lane = g & 31;

    float4 xd = ((const float4*)g_xd1)[node * 32 + lane];
    float4 av = ((const float4*)att)[lane];

    float den = 0.f;
    float4 acc = make_float4(0.f, 0.f, 0.f, 0.f);

    int j    = g_rowptr[node];
    int jend = g_rowptr[node + 1];

    for (; j + EC1 <= jend; j += EC1) {
        float4 msg[EC1];
        float  p[EC1];
        #pragma unroll
        for (int k = 0; k < EC1; k++) {
            int s = g_col[j + k];
            msg[k] = ((const float4*)g_xs1)[s * 32 + lane];
        }
        #pragma unroll
        for (int k = 0; k < EC1; k++) {
            float e0 = lrelu(msg[k].x + xd.x);
            float e1 = lrelu(msg[k].y + xd.y);
            float e2 = lrelu(msg[k].z + xd.z);
            float e3 = lrelu(msg[k].w + xd.w);
            p[k] = fmaf(av.x, e0, fmaf(av.y, e1, fmaf(av.z, e2, av.w * e3)));
        }
        #pragma unroll
        for (int k = 0; k < EC1; k++)
            p[k] += __shfl_xor_sync(0xffffffffu, p[k], 1);
        #pragma unroll
        for (int k = 0; k < EC1; k++)
            p[k] += __shfl_xor_sync(0xffffffffu, p[k], 2);
        #pragma unroll
        for (int k = 0; k < EC1; k++) {
            float w = __expf(p[k]);
            den += w;
            acc.x = fmaf(w, msg[k].x, acc.x);
            acc.y = fmaf(w, msg[k].y, acc.y);
            acc.z = fmaf(w, msg[k].z, acc.z);
            acc.w = fmaf(w, msg[k].w, acc.w);
        }
    }

    for (; j < jend; ++j) {
        int s = g_col[j];
        float4 msg = ((const float4*)g_xs1)[s * 32 + lane];
        float e0 = lrelu(msg.x + xd.x);
        float e1 = lrelu(msg.y + xd.y);
        float e2 = lrelu(msg.z + xd.z);
        float e3 = lrelu(msg.w + xd.w);
        float p = fmaf(av.x, e0, fmaf(av.y, e1, fmaf(av.z, e2, av.w * e3)));
        p += __shfl_xor_sync(0xffffffffu, p, 1);
        p += __shfl_xor_sync(0xffffffffu, p, 2);
        float w = __expf(p);
        den += w;
        acc.x = fmaf(w, msg.x, acc.x);
        acc.y = fmaf(w, msg.y, acc.y);
        acc.z = fmaf(w, msg.z, acc.z);
        acc.w = fmaf(w, msg.w, acc.w);
    }

    float inv = 1.0f / den;
    float4 b = ((const float4*)bias)[lane];
    float4 o;
    o.x = eluf(fmaf(acc.x, inv, b.x));
    o.y = eluf(fmaf(acc.y, inv, b.y));
    o.z = eluf(fmaf(acc.z, inv, b.z));
    o.w = eluf(fmaf(acc.w, inv, b.w));
    ((float4*)g_h1)[node * 32 + lane] = o;
}

// ---------------------------------------------------------------------------
// GEMM 2 (fp16 HMMA m16n8k16): [xs2|xd2] = h1[50000,128] @ [W2_src|W2_dst]
// ---------------------------------------------------------------------------
__global__ __launch_bounds__(256, 2) void k_gemm2(
    const float* __restrict__ bsrc, const float* __restrict__ bdst)
{
    __shared__ __half sAh[64][136];
    int r0 = blockIdx.x * 64;
    int t = threadIdx.x;

    #pragma unroll
    for (int i = 0; i < 8; i++) {
        int idx = t + i * 256;
        int row = idx >> 5;
        int c4  = idx & 31;
        float4 v = make_float4(0.f, 0.f, 0.f, 0.f);
        if (r0 + row < N_NODES) v = ((const float4*)g_h1)[(r0 + row) * 32 + c4];
        *(__half2*)&sAh[row][c4 * 4]     = __floats2half2_rn(v.x, v.y);
        *(__half2*)&sAh[row][c4 * 4 + 2] = __floats2half2_rn(v.z, v.w);
    }
    __syncthreads();

    int lane   = t & 31;
    int wid    = t >> 5;
    int warp_m = wid & 3;
    int warp_n = wid >> 2;
    int qid    = lane >> 2;
    int tid4   = lane & 3;

    int cbase = warp_n * 32;

    float acc[4][4];
    #pragma unroll
    for (int nt = 0; nt < 4; nt++)
        #pragma unroll
        for (int i = 0; i < 4; i++) acc[nt][i] = 0.f;

    #pragma unroll 4
    for (int ks = 0; ks < 8; ks++) {
        int k0 = ks * 16;
        unsigned a[4];
        int rb = warp_m * 16;
        a[0] = *(const unsigned*)&sAh[rb + qid    ][k0 + 2 * tid4    ];
        a[1] = *(const unsigned*)&sAh[rb + qid + 8][k0 + 2 * tid4    ];
        a[2] = *(const unsigned*)&sAh[rb + qid    ][k0 + 2 * tid4 + 8];
        a[3] = *(const unsigned*)&sAh[rb + qid + 8][k0 + 2 * tid4 + 8];

        unsigned b[4][2];
        #pragma unroll
        for (int nt = 0; nt < 4; nt++) {
            int cc = cbase + nt * 8 + qid;
            b[nt][0] = *(const unsigned*)&g_W2t[cc * 128 + k0 + 2 * tid4    ];
            b[nt][1] = *(const unsigned*)&g_W2t[cc * 128 + k0 + 2 * tid4 + 8];
        }
        #pragma unroll
        for (int nt = 0; nt < 4; nt++)
            mma_f16(acc[nt], a, b[nt]);
    }

    float* outp = warp_n ? g_xd2 : g_xs2;
    const float* bp = warp_n ? bdst : bsrc;
    int row = r0 + warp_m * 16 + qid;
    #pragma unroll
    for (int nt = 0; nt < 4; nt++) {
        int cc = nt * 8 + 2 * tid4;
        float b0v = bp[cc], b1v = bp[cc + 1];
        if (row < N_NODES) {
            float2 v = make_float2(acc[nt][0] + b0v, acc[nt][1] + b1v);
            *(float2*)&outp[row * 32 + cc] = v;
        }
        if (row + 8 < N_NODES) {
            float2 v = make_float2(acc[nt][2] + b0v, acc[nt][3] + b1v);
            *(float2*)&outp[(row + 8) * 32 + cc] = v;
        }
    }
}

// ---------------------------------------------------------------------------
// Edge phase, layer 2: one warp per node, NO-shift softmax, chunked.
// Fused with bias2 + log_softmax. Writes final output.
// ---------------------------------------------------------------------------
#define EC2 8
__global__ __launch_bounds__(256) void k_edge2(
    const float* __restrict__ att, const float* __restrict__ bias,
    float* __restrict__ out)
{
    int g = blockIdx.x * blockDim.x + threadIdx.x;
    int node = g >> 5;
    if (node >= N_NODES) return;
    int lane = g & 31;

    float xd = g_xd2[node * 32 + lane];
    float av = att[lane];

    float den = 0.f, acc = 0.f;

    int j    = g_rowptr[node];
    int jend = g_rowptr[node + 1];

    for (; j + EC2 <= jend; j += EC2) {
        float msg[EC2], p[EC2];
        #pragma unroll
        for (int k = 0; k < EC2; k++) {
            int s = g_col[j + k];
            msg[k] = g_xs2[s * 32 + lane];
        }
        #pragma unroll
        for (int k = 0; k < EC2; k++)
            p[k] = av * lrelu(msg[k] + xd);
        #pragma unroll
        for (int d = 1; d < 32; d <<= 1) {
            #pragma unroll
            for (int k = 0; k < EC2; k++)
                p[k] += __shfl_xor_sync(0xffffffffu, p[k], d);
        }
        #pragma unroll
        for (int k = 0; k < EC2; k++) {
            float w = __expf(p[k]);
            den += w;
            acc = fmaf(w, msg[k], acc);
        }
    }

    for (; j < jend; ++j) {
        int s = g_col[j];
        float msg = g_xs2[s * 32 + lane];
        float p = av * lrelu(msg + xd);
        #pragma unroll
        for (int d = 1; d < 32; d <<= 1)
            p += __shfl_xor_sync(0xffffffffu, p, d);
        float w = __expf(p);
        den += w;
        acc = fmaf(w, msg, acc);
    }

    float v = acc / den + bias[lane];

    float mx = v;
    #pragma unroll
    for (int d = 1; d < 32; d <<= 1)
        mx = fmaxf(mx, __shfl_xor_sync(0xffffffffu, mx, d));
    float ex = expf(v - mx);
    float ssum = ex;
    #pragma unroll
    for (int d = 1; d < 32; d <<= 1)
        ssum += __shfl_xor_sync(0xffffffffu, ssum, d);

    out[node * 32 + lane] = v - mx - logf(ssum);
}

// ---------------------------------------------------------------------------
// Launch: fork CSR chain (main stream) and prep+gemm1 (side stream).
// ---------------------------------------------------------------------------
extern "C" void kernel_launch(void* const* d_in, const int* in_sizes, int n_in,
                              void* d_out, int out_size)
{
    const float* x     = (const float*)d_in[0];
    const int*   ei32  = (const int*)d_in[1];   // int32 OR int64 (detected)
    const float* W1s   = (const float*)d_in[2];
    const float* W1d   = (const float*)d_in[3];
    const float* b1s   = (const float*)d_in[4];
    const float* b1d   = (const float*)d_in[5];
    const float* att1  = (const float*)d_in[6];
    const float* bias1 = (const float*)d_in[7];
    const float* W2s   = (const float*)d_in[8];
    const float* W2d   = (const float*)d_in[9];
    const float* b2s   = (const float*)d_in[10];
    const float* b2d   = (const float*)d_in[11];
    const float* att2  = (const float*)d_in[12];
    const float* bias2 = (const float*)d_in[13];
    float* out = (float*)d_out;

    static cudaStream_t s2 = nullptr;
    static cudaEvent_t evFork = nullptr, evJoin = nullptr;
    if (s2 == nullptr) {
        cudaStreamCreateWithFlags(&s2, cudaStreamNonBlocking);
        cudaEventCreateWithFlags(&evFork, cudaEventDisableTiming);
        cudaEventCreateWithFlags(&evJoin, cudaEventDisableTiming);
    }

    // Fork: side stream runs weight prep + gemm1 (independent of CSR).
    cudaEventRecord(evFork, 0);
    cudaStreamWaitEvent(s2, evFork, 0);
    k_prep<<<(256 * 128 + 255) / 256, 256, 0, s2>>>(W1s, W1d, W2s, W2d);
    k_gemm1<<<(N_NODES + 63) / 64, 256, 0, s2>>>(x, b1s, b1d);
    cudaEventRecord(evJoin, s2);

    // Main stream: CSR build chain.
    k_init<<<(N_NODES + 255) / 256, 256>>>(ei32);
    k_hist<<<(N_TOT + 255) / 256, 256>>>(ei32);
    k_scan1<<<N_CHUNKS, SCAN_CHUNK>>>();
    k_scan3<<<N_CHUNKS, SCAN_CHUNK>>>();
    k_scatter<<<(N_TOT + 255) / 256, 256>>>(ei32);

    // Join: edge1 needs both CSR and gemm1 outputs.
    cudaStreamWaitEvent(0, evJoin, 0);
    k_edge1<<<(N_NODES * 32 + 255) / 256, 256>>>(att1, bias1);

    // Layer 2
    k_gemm2<<<(N_NODES + 63) / 64, 256>>>(b2s, b2d);
    k_edge2<<<(N_NODES * 32 + 255) / 256, 256>>>(att2, bias2, out);
}